// round 8
// baseline (speedup 1.0000x reference)
#include <cuda_runtime.h>
#include <math.h>
#include <stdint.h>

#define NPIX   65536      // 256*256
#define PCOUNT 1024       // 4 * 16 * 16 patches
#define NB     512        // 8^3 bins
#define SINK_EPS 1e-6f

#define BSROW 66                          // padded floats per Bs row (conflict-free LDS.64)
#define ASROW 66                          // padded floats per As row (conflict-free STS)
#define SM_BS_FLOATS (NB * BSROW)         // 33792
#define SM_AS_FLOATS (2 * 16 * ASROW)     // 2112
#define SM_TOTAL_BYTES ((SM_BS_FLOATS + SM_AS_FLOATS) * 4)   // 143616

// ---------------- scratch (static device globals; no allocation) ----------------
__device__ float    g_oklab[2][4 * 3 * NPIX];
__device__ unsigned g_mm[12];
__device__ float    g_hist[2][PCOUNT * NB];   // [0]=hr, [1]=ht (normalized /256)
__device__ float    g_u[PCOUNT * NB];
__device__ float    g_v[PCOUNT * NB];
__device__ float    g_K[NB * NB];
__device__ float    g_KC[NB * NB];
__device__ float    g_emd[PCOUNT];
__device__ unsigned g_bar;

typedef unsigned long long ull;

__device__ __forceinline__ void ffma2(ull& d, ull a, ull b) {
    asm("fma.rn.f32x2 %0, %1, %2, %0;" : "+l"(d) : "l"(a), "l"(b));
}
__device__ __forceinline__ ull dup_f32(float x) {
    ull r;
    unsigned u = __float_as_uint(x);
    asm("mov.b64 %0, {%1, %1};" : "=l"(r) : "r"(u));
    return r;
}
__device__ __forceinline__ float lo_f(ull p) { return __uint_as_float((unsigned)p); }
__device__ __forceinline__ float hi_f(ull p) { return __uint_as_float((unsigned)(p >> 32)); }

// grid-wide barrier: all 128 CTAs co-resident (1 CTA/SM, grid < SM count)
__device__ __forceinline__ void grid_sync(unsigned target) {
    __syncthreads();
    if (threadIdx.x == 0) {
        __threadfence();
        atomicAdd(&g_bar, 1u);
        while (*(volatile unsigned*)&g_bar < target) { }
        __threadfence();
    }
    __syncthreads();
}

// ---------------- helpers ----------------
__device__ __forceinline__ unsigned fenc(float f) {
    unsigned u = __float_as_uint(f);
    return (u & 0x80000000u) ? ~u : (u | 0x80000000u);
}
__device__ __forceinline__ float fdec(unsigned u) {
    return __uint_as_float((u & 0x80000000u) ? (u ^ 0x80000000u) : ~u);
}
__device__ __forceinline__ float srgb_lin(float x) {
    x = fminf(fmaxf(x, 0.0f), 1.0f);
    return (x <= 0.04045f) ? x * (1.0f / 12.92f)
                           : powf((x + 0.055f) * (1.0f / 1.055f), 2.4f);
}
__device__ __forceinline__ void get_lohi(int img, float* lo, float* hi) {
#pragma unroll
    for (int c = 0; c < 3; c++) {
        float l = fdec(g_mm[img * 3 + c]) - 0.01f;
        float h = fdec(g_mm[6 + img * 3 + c]) + 0.01f;
        if (h - l < 1e-4f) { l -= 0.05f; h += 0.05f; }
        lo[c] = l; hi[c] = h;
    }
}

// ---------------- init: emd=0, barrier=0, minmax sentinels ----------------
__global__ void init_kernel() {
    int idx = threadIdx.x;                       // one block of 1024
    g_emd[idx] = 0.0f;
    if (idx == 0) g_bar = 0u;
    if (idx < 6) g_mm[idx] = 0xFFFFFFFFu;
    else if (idx < 12) g_mm[idx] = 0u;
}

// ---------------- sRGB -> OKLab + per-channel global min/max ----------------
__global__ void oklab_kernel(const float* __restrict__ ref, const float* __restrict__ tgt) {
    const int img = blockIdx.y;
    const float* __restrict__ in = img ? tgt : ref;
    float* __restrict__ outp = g_oklab[img];
    float mn0 = 1e30f, mn1 = 1e30f, mn2 = 1e30f;
    float mx0 = -1e30f, mx1 = -1e30f, mx2 = -1e30f;

    for (int idx = blockIdx.x * blockDim.x + threadIdx.x; idx < 4 * NPIX;
         idx += gridDim.x * blockDim.x) {
        int b = idx >> 16;
        int hw = idx & 65535;
        int base = b * 3 * NPIX + hw;
        float r  = srgb_lin(in[base]);
        float g  = srgb_lin(in[base + NPIX]);
        float bl = srgb_lin(in[base + 2 * NPIX]);
        float l = 0.4122214708f * r + 0.5363325363f * g + 0.0514459929f * bl;
        float m = 0.2119034982f * r + 0.6806995451f * g + 0.1073969566f * bl;
        float s = 0.0883024619f * r + 0.2817188376f * g + 0.6299787005f * bl;
        l = fmaxf(l, 0.0f); m = fmaxf(m, 0.0f); s = fmaxf(s, 0.0f);
        float lg = (l > 0.0f) ? cbrtf(fmaxf(l, 1e-12f)) : 0.0f;
        float mg = (m > 0.0f) ? cbrtf(fmaxf(m, 1e-12f)) : 0.0f;
        float sg = (s > 0.0f) ? cbrtf(fmaxf(s, 1e-12f)) : 0.0f;
        float L = 0.2104542553f * lg + 0.793617785f  * mg - 0.0040720468f * sg;
        float A = 1.9779984951f * lg - 2.428592205f  * mg + 0.4505937099f * sg;
        float B = 0.0259040371f * lg + 0.7827717662f * mg - 0.808675766f  * sg;
        outp[base] = L; outp[base + NPIX] = A; outp[base + 2 * NPIX] = B;
        mn0 = fminf(mn0, L); mx0 = fmaxf(mx0, L);
        mn1 = fminf(mn1, A); mx1 = fmaxf(mx1, A);
        mn2 = fminf(mn2, B); mx2 = fmaxf(mx2, B);
    }
#pragma unroll
    for (int o = 16; o > 0; o >>= 1) {
        mn0 = fminf(mn0, __shfl_down_sync(0xffffffffu, mn0, o));
        mn1 = fminf(mn1, __shfl_down_sync(0xffffffffu, mn1, o));
        mn2 = fminf(mn2, __shfl_down_sync(0xffffffffu, mn2, o));
        mx0 = fmaxf(mx0, __shfl_down_sync(0xffffffffu, mx0, o));
        mx1 = fmaxf(mx1, __shfl_down_sync(0xffffffffu, mx1, o));
        mx2 = fmaxf(mx2, __shfl_down_sync(0xffffffffu, mx2, o));
    }
    if ((threadIdx.x & 31) == 0) {
        atomicMin(&g_mm[img * 3 + 0], fenc(mn0));
        atomicMin(&g_mm[img * 3 + 1], fenc(mn1));
        atomicMin(&g_mm[img * 3 + 2], fenc(mn2));
        atomicMax(&g_mm[6 + img * 3 + 0], fenc(mx0));
        atomicMax(&g_mm[6 + img * 3 + 1], fenc(mx1));
        atomicMax(&g_mm[6 + img * 3 + 2], fenc(mx2));
    }
}

// ---------------- build K = exp(-cost/REG) and KC = K*cost on averaged grid ----------------
__global__ void buildK_kernel() {
    int i = blockIdx.x, j = threadIdx.x;
    float lor[3], hir[3], lot[3], hit[3];
    get_lohi(0, lor, hir);
    get_lohi(1, lot, hit);
    float step[3];
#pragma unroll
    for (int c = 0; c < 3; c++)
        step[c] = ((hir[c] - lor[c]) + (hit[c] - lot[c])) * 0.5f * 0.125f;
    int i0 = i >> 6, i1 = (i >> 3) & 7, i2 = i & 7;
    int j0 = j >> 6, j1 = (j >> 3) & 7, j2 = j & 7;
    float d0 = step[0] * (float)(i0 - j0);
    float d1 = step[1] * (float)(i1 - j1);
    float d2 = step[2] * (float)(i2 - j2);
    float dd = d0 * d0 + d1 * d1 + d2 * d2;
    float cost = (dd > 0.0f) ? sqrtf(dd) : 0.0f;
    float Kv = expf(-cost * 10.0f);        // REG = 0.1
    g_K[i * NB + j]  = Kv;
    g_KC[i * NB + j] = Kv * cost;
}

// ---------------- per-patch histograms (separable nearest-center binning) ----------------
__global__ void hist_kernel() {
    const int img = blockIdx.y, p = blockIdx.x, t = threadIdx.x;
    __shared__ float h[NB];
    __shared__ float lo_s[3], inv_s[3];
    if (t == 0) {
        float lo[3], hi[3];
        get_lohi(img, lo, hi);
#pragma unroll
        for (int c = 0; c < 3; c++) { lo_s[c] = lo[c]; inv_s[c] = 8.0f / (hi[c] - lo[c]); }
    }
    h[t] = 0.0f; h[t + 256] = 0.0f;
    __syncthreads();

    int b = p >> 8, ph = (p >> 4) & 15, pw = p & 15;
    int py = t >> 4, px = t & 15;
    int hh = (ph << 4) + py, ww = (pw << 4) + px;
    int base = b * 3 * NPIX + hh * 256 + ww;
    const float* ok = g_oklab[img];
    float xL = ok[base], xA = ok[base + NPIX], xB = ok[base + 2 * NPIX];
    int i0 = (int)floorf((xL - lo_s[0]) * inv_s[0]); i0 = min(7, max(0, i0));
    int i1 = (int)floorf((xA - lo_s[1]) * inv_s[1]); i1 = min(7, max(0, i1));
    int i2 = (int)floorf((xB - lo_s[2]) * inv_s[2]); i2 = min(7, max(0, i2));
    atomicAdd(&h[(i0 << 6) | (i1 << 3) | i2], 1.0f);
    __syncthreads();

    float* dst = &g_hist[img][p * NB];
    dst[t]       = h[t]       * (1.0f / 256.0f);
    dst[t + 256] = h[t + 256] * (1.0f / 256.0f);
}

// ---------------- full-K GEMM over smem-resident B ----------------
__device__ __forceinline__ void run_gemm(const float* __restrict__ Ap,
                                         float* __restrict__ Bs, float* __restrict__ As,
                                         int row0, int tid, int tx, int ty,
                                         ull acc[4][2]) {
#pragma unroll
    for (int i = 0; i < 4; i++) { acc[i][0] = 0ull; acc[i][1] = 0ull; }
    const int ra = tid >> 2, ka = (tid & 3) * 4;
    const float* Ag = Ap + (size_t)(row0 + ra) * NB + ka;

    float4 a4 = __ldcg((const float4*)Ag);
    As[(ka + 0) * ASROW + ra] = a4.x;
    As[(ka + 1) * ASROW + ra] = a4.y;
    As[(ka + 2) * ASROW + ra] = a4.z;
    As[(ka + 3) * ASROW + ra] = a4.w;
    __syncthreads();

    int buf = 0;
    for (int kc = 0; kc < 32; kc++) {
        if (kc + 1 < 32) a4 = __ldcg((const float4*)(Ag + (kc + 1) * 16));
        const float* Ab = As + buf * 16 * ASROW;
        const float* Bb = Bs + kc * 16 * BSROW;
#pragma unroll
        for (int kk = 0; kk < 16; kk++) {
            const ull* ap = (const ull*)(Ab + kk * ASROW + ty * 8);   // warp-uniform bcast
            ull a0 = ap[0], a1 = ap[1], a2 = ap[2], a3 = ap[3];
            float2 b2 = *(const float2*)(Bb + kk * BSROW + tx * 2);
            ull bb0 = dup_f32(b2.x), bb1 = dup_f32(b2.y);
            ffma2(acc[0][0], a0, bb0); ffma2(acc[0][1], a0, bb1);
            ffma2(acc[1][0], a1, bb0); ffma2(acc[1][1], a1, bb1);
            ffma2(acc[2][0], a2, bb0); ffma2(acc[2][1], a2, bb1);
            ffma2(acc[3][0], a3, bb0); ffma2(acc[3][1], a3, bb1);
        }
        if (kc + 1 < 32) {
            float* An = As + (buf ^ 1) * 16 * ASROW;
            An[(ka + 0) * ASROW + ra] = a4.x;
            An[(ka + 1) * ASROW + ra] = a4.y;
            An[(ka + 2) * ASROW + ra] = a4.z;
            An[(ka + 3) * ASROW + ra] = a4.w;
            __syncthreads();
            buf ^= 1;
        }
    }
}

// ---------------- persistent sinkhorn: all 41 phases in one kernel ----------------
__global__ void __launch_bounds__(256) sink_persist() {
    extern __shared__ float sm[];
    float* Bs = sm;                        // [512][BSROW]  K (later KC) column slice
    float* As = sm + SM_BS_FLOATS;         // [2][16][ASROW] streamed A double buffer

    const int tid = threadIdx.x;
    const int tx = tid & 31, ty = tid >> 5;
    const int row0 = (blockIdx.x >> 3) * 64;
    const int col0 = (blockIdx.x & 7) * 64;

    // load B slice: Bs[k][c] = K[col0+c][k]  (K symmetric -> coalesced row reads)
    for (int i = tid; i < 64 * NB; i += 256) {
        int c = i >> 9, k = i & 511;
        Bs[k * BSROW + c] = g_K[(size_t)(col0 + c) * NB + k];
    }
    __syncthreads();

    // ---- phase 0: v = ht / (colsum(K) + eps)   (u0 = 1) ----
    {
        int c = tid & 63, kseg = tid >> 6;
        float part = 0.0f;
        for (int k = kseg * 128; k < kseg * 128 + 128; k++) part += Bs[k * BSROW + c];
        As[(tid >> 6) * 64 + c] = part;     // scratch [4][64]
        __syncthreads();
        for (int i = tid; i < 64 * 64; i += 256) {
            int r = i >> 6, cc = i & 63;
            float s = As[cc] + As[64 + cc] + As[128 + cc] + As[192 + cc];
            size_t gi = (size_t)(row0 + r) * NB + col0 + cc;
            g_v[gi] = __fdividef(g_hist[1][gi], s + SINK_EPS);
        }
    }
    grid_sync(128u * 1);

    // ---- phases 1..39: alternate u-update (odd) / v-update (even) ----
    for (int p = 1; p < 40; p++) {
        const float* Ap  = (p & 1) ? g_v : g_u;
        const float* num = (p & 1) ? g_hist[0] : g_hist[1];
        float* outp      = (p & 1) ? g_u : g_v;

        ull acc[4][2];
        run_gemm(Ap, Bs, As, row0, tid, tx, ty, acc);

#pragma unroll
        for (int pr = 0; pr < 4; pr++) {
            int r = row0 + ty * 8 + pr * 2;
            size_t gi = (size_t)r * NB + col0 + tx * 2;
            float2 n0 = *(const float2*)(num + gi);
            float2 n1 = *(const float2*)(num + gi + NB);
            float2 o0, o1;
            o0.x = __fdividef(n0.x, lo_f(acc[pr][0]) + SINK_EPS);
            o0.y = __fdividef(n0.y, lo_f(acc[pr][1]) + SINK_EPS);
            o1.x = __fdividef(n1.x, hi_f(acc[pr][0]) + SINK_EPS);
            o1.y = __fdividef(n1.y, hi_f(acc[pr][1]) + SINK_EPS);
            *(float2*)(outp + gi) = o0;
            *(float2*)(outp + gi + NB) = o1;
        }
        grid_sync(128u * (unsigned)(p + 1));
    }

    // ---- final phase: emd[r] += sum_c u[r,c] * (v @ KC)[r,c] ----
    for (int i = tid; i < 64 * NB; i += 256) {        // swap in KC slice
        int c = i >> 9, k = i & 511;
        Bs[k * BSROW + c] = g_KC[(size_t)(col0 + c) * NB + k];
    }
    __syncthreads();
    {
        ull acc[4][2];
        run_gemm(g_v, Bs, As, row0, tid, tx, ty, acc);
#pragma unroll
        for (int pr = 0; pr < 4; pr++) {
#pragma unroll
            for (int half = 0; half < 2; half++) {
                int r = row0 + ty * 8 + pr * 2 + half;
                size_t gi = (size_t)r * NB + col0 + tx * 2;
                float2 uu = __ldcg((const float2*)(g_u + gi));
                float s = (half == 0)
                    ? (lo_f(acc[pr][0]) * uu.x + lo_f(acc[pr][1]) * uu.y)
                    : (hi_f(acc[pr][0]) * uu.x + hi_f(acc[pr][1]) * uu.y);
#pragma unroll
                for (int o = 16; o > 0; o >>= 1)
                    s += __shfl_xor_sync(0xffffffffu, s, o);
                if (tx == 0) atomicAdd(&g_emd[r], s);
            }
        }
    }
}

// ---------------- half-pixel bilinear upsample 16x16 -> 256x256 ----------------
__global__ void upsample_kernel(float* __restrict__ out) {
    int idx = blockIdx.x * blockDim.x + threadIdx.x;
    if (idx >= 4 * NPIX) return;
    int b = idx >> 16, y = (idx >> 8) & 255, x = idx & 255;
    float fy = (y + 0.5f) * 0.0625f - 0.5f;
    float fx = (x + 0.5f) * 0.0625f - 0.5f;
    int y0 = (int)floorf(fy); float wy = fy - (float)y0;
    int x0 = (int)floorf(fx); float wx = fx - (float)x0;
    int y0c = min(15, max(0, y0)), y1c = min(15, max(0, y0 + 1));
    int x0c = min(15, max(0, x0)), x1c = min(15, max(0, x0 + 1));
    const float* e = g_emd + b * 256;
    float v00 = e[y0c * 16 + x0c], v01 = e[y0c * 16 + x1c];
    float v10 = e[y1c * 16 + x0c], v11 = e[y1c * 16 + x1c];
    v00 = isfinite(v00) ? v00 : 0.0f;
    v01 = isfinite(v01) ? v01 : 0.0f;
    v10 = isfinite(v10) ? v10 : 0.0f;
    v11 = isfinite(v11) ? v11 : 0.0f;
    float t0 = v00 + (v01 - v00) * wx;
    float t1 = v10 + (v11 - v10) * wx;
    out[idx] = t0 + (t1 - t0) * wy;
}

// ---------------- launcher ----------------
extern "C" void kernel_launch(void* const* d_in, const int* in_sizes, int n_in,
                              void* d_out, int out_size) {
    (void)in_sizes; (void)n_in; (void)out_size;
    const float* ref = (const float*)d_in[0];
    const float* tgt = (const float*)d_in[1];
    float* out = (float*)d_out;

    static int smem_set = 0;
    if (!smem_set) {
        cudaFuncSetAttribute(sink_persist, cudaFuncAttributeMaxDynamicSharedMemorySize,
                             SM_TOTAL_BYTES);
        smem_set = 1;
    }

    init_kernel<<<1, 1024>>>();
    oklab_kernel<<<dim3(256, 2), 256>>>(ref, tgt);
    buildK_kernel<<<NB, NB>>>();
    hist_kernel<<<dim3(PCOUNT, 2), 256>>>();

    sink_persist<<<128, 256, SM_TOTAL_BYTES>>>();

    upsample_kernel<<<(4 * NPIX + 255) / 256, 256>>>(out);
}

// round 9
// speedup vs baseline: 1.4759x; 1.4759x over previous
#include <cuda_runtime.h>
#include <math.h>
#include <stdint.h>

#define NPIX   65536      // 256*256
#define PCOUNT 1024       // 4 * 16 * 16 patches
#define NB     512        // 8^3 bins
#define SINK_EPS 1e-6f

#define BK 16
#define KHALF 256                 // K range per CTA (split-K x2)
#define NKC (KHALF / BK)          // 16 chunks

// ---------------- scratch (static device globals; no allocation) ----------------
__device__ float    g_oklab[2][4 * 3 * NPIX];   // [img][b][c][h][w]
__device__ unsigned g_mm[12];                   // [0:6) min enc (img,c), [6:12) max enc
__device__ float    g_hist[2][PCOUNT * NB];     // normalized (counts/256)
__device__ float    g_Du[2][PCOUNT * NB];       // split-K partials of (v@K)
__device__ float    g_Dv[2][PCOUNT * NB];       // split-K partials of (u@K)
__device__ float    g_K[NB * NB];
__device__ float    g_KC[NB * NB];              // K * cost
__device__ float    g_emd[PCOUNT];

typedef unsigned long long ull;

// packed fp32x2 FMA: d = a*b + d (two independent lanes)
__device__ __forceinline__ void ffma2(ull& d, ull a, ull b) {
    asm("fma.rn.f32x2 %0, %1, %2, %0;" : "+l"(d) : "l"(a), "l"(b));
}
__device__ __forceinline__ ull dup_f32(float x) {
    ull r;
    unsigned u = __float_as_uint(x);
    asm("mov.b64 %0, {%1, %1};" : "=l"(r) : "r"(u));
    return r;
}
__device__ __forceinline__ float lo_f(ull p) { return __uint_as_float((unsigned)p); }
__device__ __forceinline__ float hi_f(ull p) { return __uint_as_float((unsigned)(p >> 32)); }

// ---------------- helpers ----------------
__device__ __forceinline__ unsigned fenc(float f) {
    unsigned u = __float_as_uint(f);
    return (u & 0x80000000u) ? ~u : (u | 0x80000000u);
}
__device__ __forceinline__ float fdec(unsigned u) {
    return __uint_as_float((u & 0x80000000u) ? (u ^ 0x80000000u) : ~u);
}
__device__ __forceinline__ float srgb_lin(float x) {
    x = fminf(fmaxf(x, 0.0f), 1.0f);
    return (x <= 0.04045f) ? x * (1.0f / 12.92f)
                           : powf((x + 0.055f) * (1.0f / 1.055f), 2.4f);
}
__device__ __forceinline__ void get_lohi(int img, float* lo, float* hi) {
#pragma unroll
    for (int c = 0; c < 3; c++) {
        float l = fdec(g_mm[img * 3 + c]) - 0.01f;
        float h = fdec(g_mm[6 + img * 3 + c]) + 0.01f;
        if (h - l < 1e-4f) { l -= 0.05f; h += 0.05f; }
        lo[c] = l; hi[c] = h;
    }
}

// ---------------- init: emd=0, minmax sentinels ----------------
__global__ void init_kernel() {
    int idx = threadIdx.x;                       // one block of 1024
    g_emd[idx] = 0.0f;
    if (idx < 6) g_mm[idx] = 0xFFFFFFFFu;
    else if (idx < 12) g_mm[idx] = 0u;
}

// ---------------- sRGB -> OKLab + per-channel global min/max ----------------
__global__ void oklab_kernel(const float* __restrict__ ref, const float* __restrict__ tgt) {
    const int img = blockIdx.y;
    const float* __restrict__ in = img ? tgt : ref;
    float* __restrict__ outp = g_oklab[img];
    float mn0 = 1e30f, mn1 = 1e30f, mn2 = 1e30f;
    float mx0 = -1e30f, mx1 = -1e30f, mx2 = -1e30f;

    for (int idx = blockIdx.x * blockDim.x + threadIdx.x; idx < 4 * NPIX;
         idx += gridDim.x * blockDim.x) {
        int b = idx >> 16;
        int hw = idx & 65535;
        int base = b * 3 * NPIX + hw;
        float r  = srgb_lin(in[base]);
        float g  = srgb_lin(in[base + NPIX]);
        float bl = srgb_lin(in[base + 2 * NPIX]);
        float l = 0.4122214708f * r + 0.5363325363f * g + 0.0514459929f * bl;
        float m = 0.2119034982f * r + 0.6806995451f * g + 0.1073969566f * bl;
        float s = 0.0883024619f * r + 0.2817188376f * g + 0.6299787005f * bl;
        l = fmaxf(l, 0.0f); m = fmaxf(m, 0.0f); s = fmaxf(s, 0.0f);
        float lg = (l > 0.0f) ? cbrtf(fmaxf(l, 1e-12f)) : 0.0f;
        float mg = (m > 0.0f) ? cbrtf(fmaxf(m, 1e-12f)) : 0.0f;
        float sg = (s > 0.0f) ? cbrtf(fmaxf(s, 1e-12f)) : 0.0f;
        float L = 0.2104542553f * lg + 0.793617785f  * mg - 0.0040720468f * sg;
        float A = 1.9779984951f * lg - 2.428592205f  * mg + 0.4505937099f * sg;
        float B = 0.0259040371f * lg + 0.7827717662f * mg - 0.808675766f  * sg;
        outp[base] = L; outp[base + NPIX] = A; outp[base + 2 * NPIX] = B;
        mn0 = fminf(mn0, L); mx0 = fmaxf(mx0, L);
        mn1 = fminf(mn1, A); mx1 = fmaxf(mx1, A);
        mn2 = fminf(mn2, B); mx2 = fmaxf(mx2, B);
    }
#pragma unroll
    for (int o = 16; o > 0; o >>= 1) {
        mn0 = fminf(mn0, __shfl_down_sync(0xffffffffu, mn0, o));
        mn1 = fminf(mn1, __shfl_down_sync(0xffffffffu, mn1, o));
        mn2 = fminf(mn2, __shfl_down_sync(0xffffffffu, mn2, o));
        mx0 = fmaxf(mx0, __shfl_down_sync(0xffffffffu, mx0, o));
        mx1 = fmaxf(mx1, __shfl_down_sync(0xffffffffu, mx1, o));
        mx2 = fmaxf(mx2, __shfl_down_sync(0xffffffffu, mx2, o));
    }
    if ((threadIdx.x & 31) == 0) {
        atomicMin(&g_mm[img * 3 + 0], fenc(mn0));
        atomicMin(&g_mm[img * 3 + 1], fenc(mn1));
        atomicMin(&g_mm[img * 3 + 2], fenc(mn2));
        atomicMax(&g_mm[6 + img * 3 + 0], fenc(mx0));
        atomicMax(&g_mm[6 + img * 3 + 1], fenc(mx1));
        atomicMax(&g_mm[6 + img * 3 + 2], fenc(mx2));
    }
}

// ---------------- build K = exp(-cost/REG) and KC = K*cost on averaged grid ----------------
__global__ void buildK_kernel() {
    int i = blockIdx.x, j = threadIdx.x;
    float lor[3], hir[3], lot[3], hit[3];
    get_lohi(0, lor, hir);
    get_lohi(1, lot, hit);
    float step[3];
#pragma unroll
    for (int c = 0; c < 3; c++)
        step[c] = ((hir[c] - lor[c]) + (hit[c] - lot[c])) * 0.5f * 0.125f;
    int i0 = i >> 6, i1 = (i >> 3) & 7, i2 = i & 7;
    int j0 = j >> 6, j1 = (j >> 3) & 7, j2 = j & 7;
    float d0 = step[0] * (float)(i0 - j0);
    float d1 = step[1] * (float)(i1 - j1);
    float d2 = step[2] * (float)(i2 - j2);
    float dd = d0 * d0 + d1 * d1 + d2 * d2;
    float cost = (dd > 0.0f) ? sqrtf(dd) : 0.0f;
    float Kv = expf(-cost * 10.0f);        // REG = 0.1
    g_K[i * NB + j]  = Kv;
    g_KC[i * NB + j] = Kv * cost;
}

// ---------------- per-patch histograms (separable nearest-center binning) ----------------
__global__ void hist_kernel() {
    const int img = blockIdx.y, p = blockIdx.x, t = threadIdx.x;
    __shared__ float h[NB];
    __shared__ float lo_s[3], inv_s[3];
    if (t == 0) {
        float lo[3], hi[3];
        get_lohi(img, lo, hi);
#pragma unroll
        for (int c = 0; c < 3; c++) { lo_s[c] = lo[c]; inv_s[c] = 8.0f / (hi[c] - lo[c]); }
    }
    h[t] = 0.0f; h[t + 256] = 0.0f;
    __syncthreads();

    int b = p >> 8, ph = (p >> 4) & 15, pw = p & 15;
    int py = t >> 4, px = t & 15;
    int hh = (ph << 4) + py, ww = (pw << 4) + px;
    int base = b * 3 * NPIX + hh * 256 + ww;
    const float* ok = g_oklab[img];
    float xL = ok[base], xA = ok[base + NPIX], xB = ok[base + 2 * NPIX];
    int i0 = (int)floorf((xL - lo_s[0]) * inv_s[0]); i0 = min(7, max(0, i0));
    int i1 = (int)floorf((xA - lo_s[1]) * inv_s[1]); i1 = min(7, max(0, i1));
    int i2 = (int)floorf((xB - lo_s[2]) * inv_s[2]); i2 = min(7, max(0, i2));
    atomicAdd(&h[(i0 << 6) | (i1 << 3) | i2], 1.0f);
    __syncthreads();

    float* dst = &g_hist[img][p * NB];
    dst[t]       = h[t]       * (1.0f / 256.0f);
    dst[t + 256] = h[t + 256] * (1.0f / 256.0f);
}

// ---------------- sinkhorn GEMM: split-K CTAs, lazy reconstruction, 512 threads ------
// A-operand is reconstructed on load as numerA/(Da0+Da1+eps) (or ones for mode 0).
// Output = raw partial (A @ Km) for this CTA's K-half.
// mode 0: first v-update: A=1,        out g_Dv[kh], Km=K
// mode 1: v-update:       A=u(recon), out g_Dv[kh], Km=K   (numer=hr, D=g_Du)
// mode 2: u-update:       A=v(recon), out g_Du[kh], Km=K   (numer=ht, D=g_Dv)
// mode 3: emd:            A=v(recon), Km=KC; epilogue dots with u(recon), atomicAdd g_emd
__global__ void __launch_bounds__(512) sink_kernel(int mode) {
    __shared__ float As[2][BK][64];      // 8KB
    __shared__ float Bs[2][BK][128];     // 16KB

    const int tid = threadIdx.x;
    const int tx = tid & 31;             // lane -> cols tx*4 .. tx*4+3
    const int ty = tid >> 5;             // warp (0..15) -> rows ty*4 .. ty*4+3 (2 pairs)
    const int col0 = blockIdx.x * 128;
    const int row0 = blockIdx.y * 64;
    const int kh = blockIdx.z;
    const int koff = kh * KHALF;

    const float *numerA = nullptr, *Da0 = nullptr, *Da1 = nullptr;
    const float* Km = g_K;
    float* outD = nullptr;
    const bool ones = (mode == 0);
    if (mode == 0)      { outD = g_Dv[kh]; }
    else if (mode == 1) { numerA = g_hist[0]; Da0 = g_Du[0]; Da1 = g_Du[1]; outD = g_Dv[kh]; }
    else if (mode == 2) { numerA = g_hist[1]; Da0 = g_Dv[0]; Da1 = g_Dv[1]; outD = g_Du[kh]; }
    else                { numerA = g_hist[1]; Da0 = g_Dv[0]; Da1 = g_Dv[1]; Km = g_KC; }

    // loaders (512 threads)
    const int ra = tid >> 3, ka = (tid & 7) * 2;        // A: 64 rows x 16k, float2 each
    const int kb = tid >> 5, nbo = (tid & 31) * 4;      // B: 16k x 128n, float4 each
    const size_t aoff = (size_t)(row0 + ra) * NB + koff + ka;
    const size_t boff = (size_t)(koff + kb) * NB + col0 + nbo;

    if (ones) {     // A tile is all-ones for the whole kernel; fill both buffers once
        float* af = (float*)As;
        for (int i = tid; i < 2 * BK * 64; i += 512) af[i] = 1.0f;
    }

    ull acc[2][4];
#pragma unroll
    for (int i = 0; i < 2; i++)
#pragma unroll
        for (int j = 0; j < 4; j++) acc[i][j] = 0ull;

    // prologue: load chunk 0
    float2 an, ad0, ad1;
    float4 b4;
    if (!ones) {
        an  = *(const float2*)(numerA + aoff);
        ad0 = *(const float2*)(Da0 + aoff);
        ad1 = *(const float2*)(Da1 + aoff);
    }
    b4 = *(const float4*)(Km + boff);
    if (!ones) {
        As[0][ka + 0][ra] = __fdividef(an.x, ad0.x + ad1.x + SINK_EPS);
        As[0][ka + 1][ra] = __fdividef(an.y, ad0.y + ad1.y + SINK_EPS);
    }
    *(float4*)(&Bs[0][kb][nbo]) = b4;
    __syncthreads();

    int buf = 0;
    for (int kc = 0; kc < NKC; kc++) {
        if (kc + 1 < NKC) {
            if (!ones) {
                an  = *(const float2*)(numerA + aoff + (kc + 1) * BK);
                ad0 = *(const float2*)(Da0 + aoff + (kc + 1) * BK);
                ad1 = *(const float2*)(Da1 + aoff + (kc + 1) * BK);
            }
            b4 = *(const float4*)(Km + boff + (size_t)(kc + 1) * BK * NB);
        }
#pragma unroll
        for (int kk = 0; kk < BK; kk++) {
            const ull* ap = (const ull*)(&As[buf][kk][ty * 4]);   // warp-uniform -> broadcast
            ull a0p = ap[0], a1p = ap[1];
            float4 bq = *(const float4*)(&Bs[buf][kk][tx * 4]);
            ull bb0 = dup_f32(bq.x), bb1 = dup_f32(bq.y);
            ull bb2 = dup_f32(bq.z), bb3 = dup_f32(bq.w);
            ffma2(acc[0][0], a0p, bb0); ffma2(acc[0][1], a0p, bb1);
            ffma2(acc[0][2], a0p, bb2); ffma2(acc[0][3], a0p, bb3);
            ffma2(acc[1][0], a1p, bb0); ffma2(acc[1][1], a1p, bb1);
            ffma2(acc[1][2], a1p, bb2); ffma2(acc[1][3], a1p, bb3);
        }
        if (kc + 1 < NKC) {
            int nbuf = buf ^ 1;
            if (!ones) {
                As[nbuf][ka + 0][ra] = __fdividef(an.x, ad0.x + ad1.x + SINK_EPS);
                As[nbuf][ka + 1][ra] = __fdividef(an.y, ad0.y + ad1.y + SINK_EPS);
            }
            *(float4*)(&Bs[nbuf][kb][nbo]) = b4;
            __syncthreads();
            buf = nbuf;
        }
    }

    if (mode != 3) {
        // store raw partials (coalesced float4 per row)
#pragma unroll
        for (int pr = 0; pr < 2; pr++) {
            int rlo = row0 + ty * 4 + pr * 2;
            size_t gi = (size_t)rlo * NB + col0 + tx * 4;
            float4 olo = make_float4(lo_f(acc[pr][0]), lo_f(acc[pr][1]),
                                     lo_f(acc[pr][2]), lo_f(acc[pr][3]));
            float4 ohi = make_float4(hi_f(acc[pr][0]), hi_f(acc[pr][1]),
                                     hi_f(acc[pr][2]), hi_f(acc[pr][3]));
            *(float4*)(outD + gi)      = olo;
            *(float4*)(outD + gi + NB) = ohi;
        }
    } else {
        // emd partial: sum over this CTA's N-range of u(r,c) * P(r,c)
        const float* hr  = g_hist[0];
        const float* du0 = g_Du[0];
        const float* du1 = g_Du[1];
#pragma unroll
        for (int pr = 0; pr < 2; pr++) {
#pragma unroll
            for (int half = 0; half < 2; half++) {
                int r = row0 + ty * 4 + pr * 2 + half;
                size_t gi = (size_t)r * NB + col0 + tx * 4;
                float4 n4 = *(const float4*)(hr + gi);
                float4 d0 = *(const float4*)(du0 + gi);
                float4 d1 = *(const float4*)(du1 + gi);
                float u0 = __fdividef(n4.x, d0.x + d1.x + SINK_EPS);
                float u1 = __fdividef(n4.y, d0.y + d1.y + SINK_EPS);
                float u2 = __fdividef(n4.z, d0.z + d1.z + SINK_EPS);
                float u3 = __fdividef(n4.w, d0.w + d1.w + SINK_EPS);
                float s;
                if (half == 0)
                    s = lo_f(acc[pr][0]) * u0 + lo_f(acc[pr][1]) * u1
                      + lo_f(acc[pr][2]) * u2 + lo_f(acc[pr][3]) * u3;
                else
                    s = hi_f(acc[pr][0]) * u0 + hi_f(acc[pr][1]) * u1
                      + hi_f(acc[pr][2]) * u2 + hi_f(acc[pr][3]) * u3;
#pragma unroll
                for (int o = 16; o > 0; o >>= 1)
                    s += __shfl_xor_sync(0xffffffffu, s, o);
                if (tx == 0) atomicAdd(&g_emd[r], s);
            }
        }
    }
}

// ---------------- half-pixel bilinear upsample 16x16 -> 256x256 ----------------
__global__ void upsample_kernel(float* __restrict__ out) {
    int idx = blockIdx.x * blockDim.x + threadIdx.x;
    if (idx >= 4 * NPIX) return;
    int b = idx >> 16, y = (idx >> 8) & 255, x = idx & 255;
    float fy = (y + 0.5f) * 0.0625f - 0.5f;
    float fx = (x + 0.5f) * 0.0625f - 0.5f;
    int y0 = (int)floorf(fy); float wy = fy - (float)y0;
    int x0 = (int)floorf(fx); float wx = fx - (float)x0;
    int y0c = min(15, max(0, y0)), y1c = min(15, max(0, y0 + 1));
    int x0c = min(15, max(0, x0)), x1c = min(15, max(0, x0 + 1));
    const float* e = g_emd + b * 256;
    float v00 = e[y0c * 16 + x0c], v01 = e[y0c * 16 + x1c];
    float v10 = e[y1c * 16 + x0c], v11 = e[y1c * 16 + x1c];
    v00 = isfinite(v00) ? v00 : 0.0f;
    v01 = isfinite(v01) ? v01 : 0.0f;
    v10 = isfinite(v10) ? v10 : 0.0f;
    v11 = isfinite(v11) ? v11 : 0.0f;
    float t0 = v00 + (v01 - v00) * wx;
    float t1 = v10 + (v11 - v10) * wx;
    out[idx] = t0 + (t1 - t0) * wy;
}

// ---------------- launcher ----------------
extern "C" void kernel_launch(void* const* d_in, const int* in_sizes, int n_in,
                              void* d_out, int out_size) {
    (void)in_sizes; (void)n_in; (void)out_size;
    const float* ref = (const float*)d_in[0];
    const float* tgt = (const float*)d_in[1];
    float* out = (float*)d_out;

    init_kernel<<<1, 1024>>>();
    oklab_kernel<<<dim3(256, 2), 256>>>(ref, tgt);
    buildK_kernel<<<NB, NB>>>();
    hist_kernel<<<dim3(PCOUNT, 2), 256>>>();

    dim3 gg(NB / 128, PCOUNT / 64, 2);                  // (4, 16, 2) = 128 CTAs
    sink_kernel<<<gg, 512>>>(0);                        // v-update, A = ones
    sink_kernel<<<gg, 512>>>(2);                        // u-update
    for (int it = 1; it < 20; it++) {
        sink_kernel<<<gg, 512>>>(1);                    // v-update
        sink_kernel<<<gg, 512>>>(2);                    // u-update
    }
    sink_kernel<<<gg, 512>>>(3);                        // emd accumulation

    upsample_kernel<<<(4 * NPIX + 255) / 256, 256>>>(out);
}

// round 10
// speedup vs baseline: 1.5039x; 1.0189x over previous
#include <cuda_runtime.h>
#include <math.h>
#include <stdint.h>

#define NPIX   65536      // 256*256
#define PCOUNT 1024       // 4 * 16 * 16 patches
#define NB     512        // 8^3 bins
#define SINK_EPS 1e-6f

#define BK 16
#define KHALF 256                 // K range per CTA (split-K x2)
#define NKC (KHALF / BK)          // 16 chunks
#define ASR 66                    // padded A-row stride (floats): 8B-aligned, conflict-free STS

// ---------------- scratch (static device globals; no allocation) ----------------
__device__ float    g_oklab[2][4 * 3 * NPIX];   // [img][b][c][h][w]
__device__ unsigned g_mm[12];                   // [0:6) min enc (img,c), [6:12) max enc
__device__ float    g_hist[2][PCOUNT * NB];     // normalized (counts/256)
__device__ float    g_Du[2][PCOUNT * NB];       // split-K partials of (v@K)
__device__ float    g_Dv[2][PCOUNT * NB];       // split-K partials of (u@K)
__device__ float    g_K[NB * NB];
__device__ float    g_KC[NB * NB];              // K * cost
__device__ float    g_emd[PCOUNT];

typedef unsigned long long ull;

// packed fp32x2 FMA: d = a*b + d (two independent lanes)
__device__ __forceinline__ void ffma2(ull& d, ull a, ull b) {
    asm("fma.rn.f32x2 %0, %1, %2, %0;" : "+l"(d) : "l"(a), "l"(b));
}
__device__ __forceinline__ ull dup_f32(float x) {
    ull r;
    unsigned u = __float_as_uint(x);
    asm("mov.b64 %0, {%1, %1};" : "=l"(r) : "r"(u));
    return r;
}
__device__ __forceinline__ float lo_f(ull p) { return __uint_as_float((unsigned)p); }
__device__ __forceinline__ float hi_f(ull p) { return __uint_as_float((unsigned)(p >> 32)); }

// ---------------- helpers ----------------
__device__ __forceinline__ unsigned fenc(float f) {
    unsigned u = __float_as_uint(f);
    return (u & 0x80000000u) ? ~u : (u | 0x80000000u);
}
__device__ __forceinline__ float fdec(unsigned u) {
    return __uint_as_float((u & 0x80000000u) ? (u ^ 0x80000000u) : ~u);
}
__device__ __forceinline__ float srgb_lin(float x) {
    x = fminf(fmaxf(x, 0.0f), 1.0f);
    return (x <= 0.04045f) ? x * (1.0f / 12.92f)
                           : powf((x + 0.055f) * (1.0f / 1.055f), 2.4f);
}
__device__ __forceinline__ void get_lohi(int img, float* lo, float* hi) {
#pragma unroll
    for (int c = 0; c < 3; c++) {
        float l = fdec(g_mm[img * 3 + c]) - 0.01f;
        float h = fdec(g_mm[6 + img * 3 + c]) + 0.01f;
        if (h - l < 1e-4f) { l -= 0.05f; h += 0.05f; }
        lo[c] = l; hi[c] = h;
    }
}

// ---------------- init: emd=0, minmax sentinels ----------------
__global__ void init_kernel() {
    int idx = threadIdx.x;                       // one block of 1024
    g_emd[idx] = 0.0f;
    if (idx < 6) g_mm[idx] = 0xFFFFFFFFu;
    else if (idx < 12) g_mm[idx] = 0u;
}

// ---------------- sRGB -> OKLab + per-channel global min/max ----------------
__global__ void oklab_kernel(const float* __restrict__ ref, const float* __restrict__ tgt) {
    const int img = blockIdx.y;
    const float* __restrict__ in = img ? tgt : ref;
    float* __restrict__ outp = g_oklab[img];
    float mn0 = 1e30f, mn1 = 1e30f, mn2 = 1e30f;
    float mx0 = -1e30f, mx1 = -1e30f, mx2 = -1e30f;

    for (int idx = blockIdx.x * blockDim.x + threadIdx.x; idx < 4 * NPIX;
         idx += gridDim.x * blockDim.x) {
        int b = idx >> 16;
        int hw = idx & 65535;
        int base = b * 3 * NPIX + hw;
        float r  = srgb_lin(in[base]);
        float g  = srgb_lin(in[base + NPIX]);
        float bl = srgb_lin(in[base + 2 * NPIX]);
        float l = 0.4122214708f * r + 0.5363325363f * g + 0.0514459929f * bl;
        float m = 0.2119034982f * r + 0.6806995451f * g + 0.1073969566f * bl;
        float s = 0.0883024619f * r + 0.2817188376f * g + 0.6299787005f * bl;
        l = fmaxf(l, 0.0f); m = fmaxf(m, 0.0f); s = fmaxf(s, 0.0f);
        float lg = (l > 0.0f) ? cbrtf(fmaxf(l, 1e-12f)) : 0.0f;
        float mg = (m > 0.0f) ? cbrtf(fmaxf(m, 1e-12f)) : 0.0f;
        float sg = (s > 0.0f) ? cbrtf(fmaxf(s, 1e-12f)) : 0.0f;
        float L = 0.2104542553f * lg + 0.793617785f  * mg - 0.0040720468f * sg;
        float A = 1.9779984951f * lg - 2.428592205f  * mg + 0.4505937099f * sg;
        float B = 0.0259040371f * lg + 0.7827717662f * mg - 0.808675766f  * sg;
        outp[base] = L; outp[base + NPIX] = A; outp[base + 2 * NPIX] = B;
        mn0 = fminf(mn0, L); mx0 = fmaxf(mx0, L);
        mn1 = fminf(mn1, A); mx1 = fmaxf(mx1, A);
        mn2 = fminf(mn2, B); mx2 = fmaxf(mx2, B);
    }
#pragma unroll
    for (int o = 16; o > 0; o >>= 1) {
        mn0 = fminf(mn0, __shfl_down_sync(0xffffffffu, mn0, o));
        mn1 = fminf(mn1, __shfl_down_sync(0xffffffffu, mn1, o));
        mn2 = fminf(mn2, __shfl_down_sync(0xffffffffu, mn2, o));
        mx0 = fmaxf(mx0, __shfl_down_sync(0xffffffffu, mx0, o));
        mx1 = fmaxf(mx1, __shfl_down_sync(0xffffffffu, mx1, o));
        mx2 = fmaxf(mx2, __shfl_down_sync(0xffffffffu, mx2, o));
    }
    if ((threadIdx.x & 31) == 0) {
        atomicMin(&g_mm[img * 3 + 0], fenc(mn0));
        atomicMin(&g_mm[img * 3 + 1], fenc(mn1));
        atomicMin(&g_mm[img * 3 + 2], fenc(mn2));
        atomicMax(&g_mm[6 + img * 3 + 0], fenc(mx0));
        atomicMax(&g_mm[6 + img * 3 + 1], fenc(mx1));
        atomicMax(&g_mm[6 + img * 3 + 2], fenc(mx2));
    }
}

// ---------------- build K = exp(-cost/REG) and KC = K*cost on averaged grid ----------------
__global__ void buildK_kernel() {
    int i = blockIdx.x, j = threadIdx.x;
    float lor[3], hir[3], lot[3], hit[3];
    get_lohi(0, lor, hir);
    get_lohi(1, lot, hit);
    float step[3];
#pragma unroll
    for (int c = 0; c < 3; c++)
        step[c] = ((hir[c] - lor[c]) + (hit[c] - lot[c])) * 0.5f * 0.125f;
    int i0 = i >> 6, i1 = (i >> 3) & 7, i2 = i & 7;
    int j0 = j >> 6, j1 = (j >> 3) & 7, j2 = j & 7;
    float d0 = step[0] * (float)(i0 - j0);
    float d1 = step[1] * (float)(i1 - j1);
    float d2 = step[2] * (float)(i2 - j2);
    float dd = d0 * d0 + d1 * d1 + d2 * d2;
    float cost = (dd > 0.0f) ? sqrtf(dd) : 0.0f;
    float Kv = expf(-cost * 10.0f);        // REG = 0.1
    g_K[i * NB + j]  = Kv;
    g_KC[i * NB + j] = Kv * cost;
}

// ---------------- per-patch histograms (separable nearest-center binning) ----------------
__global__ void hist_kernel() {
    const int img = blockIdx.y, p = blockIdx.x, t = threadIdx.x;
    __shared__ float h[NB];
    __shared__ float lo_s[3], inv_s[3];
    if (t == 0) {
        float lo[3], hi[3];
        get_lohi(img, lo, hi);
#pragma unroll
        for (int c = 0; c < 3; c++) { lo_s[c] = lo[c]; inv_s[c] = 8.0f / (hi[c] - lo[c]); }
    }
    h[t] = 0.0f; h[t + 256] = 0.0f;
    __syncthreads();

    int b = p >> 8, ph = (p >> 4) & 15, pw = p & 15;
    int py = t >> 4, px = t & 15;
    int hh = (ph << 4) + py, ww = (pw << 4) + px;
    int base = b * 3 * NPIX + hh * 256 + ww;
    const float* ok = g_oklab[img];
    float xL = ok[base], xA = ok[base + NPIX], xB = ok[base + 2 * NPIX];
    int i0 = (int)floorf((xL - lo_s[0]) * inv_s[0]); i0 = min(7, max(0, i0));
    int i1 = (int)floorf((xA - lo_s[1]) * inv_s[1]); i1 = min(7, max(0, i1));
    int i2 = (int)floorf((xB - lo_s[2]) * inv_s[2]); i2 = min(7, max(0, i2));
    atomicAdd(&h[(i0 << 6) | (i1 << 3) | i2], 1.0f);
    __syncthreads();

    float* dst = &g_hist[img][p * NB];
    dst[t]       = h[t]       * (1.0f / 256.0f);
    dst[t + 256] = h[t + 256] * (1.0f / 256.0f);
}

// ---------------- sinkhorn GEMM: split-K CTAs, lazy recon, 2 CTAs/SM, 64-col tile ----
// A-operand reconstructed on load as numerA/(Da0+Da1+eps) (or ones for mode 0).
// Output = raw partial (A @ Km) for this CTA's K-half.
// mode 0: first v-update: A=1,        out g_Dv[kh], Km=K
// mode 1: v-update:       A=u(recon), out g_Dv[kh], Km=K   (numer=hr, D=g_Du)
// mode 2: u-update:       A=v(recon), out g_Du[kh], Km=K   (numer=ht, D=g_Dv)
// mode 3: emd:            A=v(recon), Km=KC; epilogue dots with u(recon), atomicAdd g_emd
__global__ void __launch_bounds__(256, 2) sink_kernel(int mode) {
    __shared__ float As[2][BK][ASR];     // ~8.25KB (padded, conflict-free STS + 8B-aligned)
    __shared__ float Bs[2][BK][64];      // 8KB

    const int tid = threadIdx.x;
    const int tx = tid & 31;             // lane -> cols tx*2, tx*2+1
    const int ty = tid >> 5;             // warp (0..7) -> rows ty*8 .. ty*8+7 (4 pairs)
    const int col0 = blockIdx.x * 64;
    const int row0 = blockIdx.y * 64;
    const int kh = blockIdx.z;
    const int koff = kh * KHALF;

    const float *numerA = nullptr, *Da0 = nullptr, *Da1 = nullptr;
    const float* Km = g_K;
    float* outD = nullptr;
    const bool ones = (mode == 0);
    if (mode == 0)      { outD = g_Dv[kh]; }
    else if (mode == 1) { numerA = g_hist[0]; Da0 = g_Du[0]; Da1 = g_Du[1]; outD = g_Dv[kh]; }
    else if (mode == 2) { numerA = g_hist[1]; Da0 = g_Dv[0]; Da1 = g_Dv[1]; outD = g_Du[kh]; }
    else                { numerA = g_hist[1]; Da0 = g_Dv[0]; Da1 = g_Dv[1]; Km = g_KC; }

    // loaders (256 threads)
    const int ra = tid >> 2, ka = (tid & 3) * 4;        // A: 64 rows x 16k, float4 each
    const int kb = tid >> 4, nbo = (tid & 15) * 4;      // B: 16k x 64n, float4 each
    const size_t aoff = (size_t)(row0 + ra) * NB + koff + ka;
    const size_t boff = (size_t)(koff + kb) * NB + col0 + nbo;

    if (ones) {     // A tile is all-ones for the whole kernel; fill both buffers once
        float* af = (float*)As;
        for (int i = tid; i < 2 * BK * ASR; i += 256) af[i] = 1.0f;
    }

    ull acc[4][2];
#pragma unroll
    for (int i = 0; i < 4; i++) { acc[i][0] = 0ull; acc[i][1] = 0ull; }

    // prologue: load chunk 0
    float4 an, ad0, ad1, b4;
    if (!ones) {
        an  = *(const float4*)(numerA + aoff);
        ad0 = *(const float4*)(Da0 + aoff);
        ad1 = *(const float4*)(Da1 + aoff);
    }
    b4 = *(const float4*)(Km + boff);
    if (!ones) {
        As[0][ka + 0][ra] = __fdividef(an.x, ad0.x + ad1.x + SINK_EPS);
        As[0][ka + 1][ra] = __fdividef(an.y, ad0.y + ad1.y + SINK_EPS);
        As[0][ka + 2][ra] = __fdividef(an.z, ad0.z + ad1.z + SINK_EPS);
        As[0][ka + 3][ra] = __fdividef(an.w, ad0.w + ad1.w + SINK_EPS);
    }
    *(float4*)(&Bs[0][kb][nbo]) = b4;
    __syncthreads();

    int buf = 0;
    for (int kc = 0; kc < NKC; kc++) {
        if (kc + 1 < NKC) {
            if (!ones) {
                an  = *(const float4*)(numerA + aoff + (kc + 1) * BK);
                ad0 = *(const float4*)(Da0 + aoff + (kc + 1) * BK);
                ad1 = *(const float4*)(Da1 + aoff + (kc + 1) * BK);
            }
            b4 = *(const float4*)(Km + boff + (size_t)(kc + 1) * BK * NB);
        }
#pragma unroll
        for (int kk = 0; kk < BK; kk++) {
            const ull* ap = (const ull*)(&As[buf][kk][ty * 8]);   // warp-uniform -> broadcast
            ull a0p = ap[0], a1p = ap[1], a2p = ap[2], a3p = ap[3];
            float2 bq = *(const float2*)(&Bs[buf][kk][tx * 2]);
            ull bb0 = dup_f32(bq.x), bb1 = dup_f32(bq.y);
            ffma2(acc[0][0], a0p, bb0); ffma2(acc[0][1], a0p, bb1);
            ffma2(acc[1][0], a1p, bb0); ffma2(acc[1][1], a1p, bb1);
            ffma2(acc[2][0], a2p, bb0); ffma2(acc[2][1], a2p, bb1);
            ffma2(acc[3][0], a3p, bb0); ffma2(acc[3][1], a3p, bb1);
        }
        if (kc + 1 < NKC) {
            int nbuf = buf ^ 1;
            if (!ones) {
                As[nbuf][ka + 0][ra] = __fdividef(an.x, ad0.x + ad1.x + SINK_EPS);
                As[nbuf][ka + 1][ra] = __fdividef(an.y, ad0.y + ad1.y + SINK_EPS);
                As[nbuf][ka + 2][ra] = __fdividef(an.z, ad0.z + ad1.z + SINK_EPS);
                As[nbuf][ka + 3][ra] = __fdividef(an.w, ad0.w + ad1.w + SINK_EPS);
            }
            *(float4*)(&Bs[nbuf][kb][nbo]) = b4;
            __syncthreads();
            buf = nbuf;
        }
    }

    if (mode != 3) {
        // store raw partials (coalesced float2 per row: warp covers 64 cols = 256B)
#pragma unroll
        for (int pr = 0; pr < 4; pr++) {
            int rlo = row0 + ty * 8 + pr * 2;
            size_t gi = (size_t)rlo * NB + col0 + tx * 2;
            *(float2*)(outD + gi)      = make_float2(lo_f(acc[pr][0]), lo_f(acc[pr][1]));
            *(float2*)(outD + gi + NB) = make_float2(hi_f(acc[pr][0]), hi_f(acc[pr][1]));
        }
    } else {
        // emd partial: sum over this CTA's N-range of u(r,c) * P(r,c)
        const float* hr  = g_hist[0];
        const float* du0 = g_Du[0];
        const float* du1 = g_Du[1];
#pragma unroll
        for (int pr = 0; pr < 4; pr++) {
#pragma unroll
            for (int half = 0; half < 2; half++) {
                int r = row0 + ty * 8 + pr * 2 + half;
                size_t gi = (size_t)r * NB + col0 + tx * 2;
                float2 n2 = *(const float2*)(hr + gi);
                float2 d0 = *(const float2*)(du0 + gi);
                float2 d1 = *(const float2*)(du1 + gi);
                float u0 = __fdividef(n2.x, d0.x + d1.x + SINK_EPS);
                float u1 = __fdividef(n2.y, d0.y + d1.y + SINK_EPS);
                float s;
                if (half == 0)
                    s = lo_f(acc[pr][0]) * u0 + lo_f(acc[pr][1]) * u1;
                else
                    s = hi_f(acc[pr][0]) * u0 + hi_f(acc[pr][1]) * u1;
#pragma unroll
                for (int o = 16; o > 0; o >>= 1)
                    s += __shfl_xor_sync(0xffffffffu, s, o);
                if (tx == 0) atomicAdd(&g_emd[r], s);
            }
        }
    }
}

// ---------------- half-pixel bilinear upsample 16x16 -> 256x256 ----------------
__global__ void upsample_kernel(float* __restrict__ out) {
    int idx = blockIdx.x * blockDim.x + threadIdx.x;
    if (idx >= 4 * NPIX) return;
    int b = idx >> 16, y = (idx >> 8) & 255, x = idx & 255;
    float fy = (y + 0.5f) * 0.0625f - 0.5f;
    float fx = (x + 0.5f) * 0.0625f - 0.5f;
    int y0 = (int)floorf(fy); float wy = fy - (float)y0;
    int x0 = (int)floorf(fx); float wx = fx - (float)x0;
    int y0c = min(15, max(0, y0)), y1c = min(15, max(0, y0 + 1));
    int x0c = min(15, max(0, x0)), x1c = min(15, max(0, x0 + 1));
    const float* e = g_emd + b * 256;
    float v00 = e[y0c * 16 + x0c], v01 = e[y0c * 16 + x1c];
    float v10 = e[y1c * 16 + x0c], v11 = e[y1c * 16 + x1c];
    v00 = isfinite(v00) ? v00 : 0.0f;
    v01 = isfinite(v01) ? v01 : 0.0f;
    v10 = isfinite(v10) ? v10 : 0.0f;
    v11 = isfinite(v11) ? v11 : 0.0f;
    float t0 = v00 + (v01 - v00) * wx;
    float t1 = v10 + (v11 - v10) * wx;
    out[idx] = t0 + (t1 - t0) * wy;
}

// ---------------- launcher ----------------
extern "C" void kernel_launch(void* const* d_in, const int* in_sizes, int n_in,
                              void* d_out, int out_size) {
    (void)in_sizes; (void)n_in; (void)out_size;
    const float* ref = (const float*)d_in[0];
    const float* tgt = (const float*)d_in[1];
    float* out = (float*)d_out;

    init_kernel<<<1, 1024>>>();
    oklab_kernel<<<dim3(256, 2), 256>>>(ref, tgt);
    buildK_kernel<<<NB, NB>>>();
    hist_kernel<<<dim3(PCOUNT, 2), 256>>>();

    dim3 gg(NB / 64, PCOUNT / 64, 2);                   // (8, 16, 2) = 256 CTAs, 2/SM
    sink_kernel<<<gg, 256>>>(0);                        // v-update, A = ones
    sink_kernel<<<gg, 256>>>(2);                        // u-update
    for (int it = 1; it < 20; it++) {
        sink_kernel<<<gg, 256>>>(1);                    // v-update
        sink_kernel<<<gg, 256>>>(2);                    // u-update
    }
    sink_kernel<<<gg, 256>>>(3);                        // emd accumulation

    upsample_kernel<<<(4 * NPIX + 255) / 256, 256>>>(out);
}

// round 11
// speedup vs baseline: 2.1963x; 1.4604x over previous
#include <cuda_runtime.h>
#include <cuda_fp16.h>
#include <math.h>
#include <stdint.h>

#define NPIX   65536      // 256*256
#define PCOUNT 1024       // 4 * 16 * 16 patches
#define NB     512        // 8^3 bins
#define SINK_EPS 1e-6f

// sink kernel smem: 230400 bytes dynamic
#define SINK_SMEM_BYTES 230400
#define SINK_SMEM_WORDS (SINK_SMEM_BYTES / 4)   // 57600
#define AUX_WORDS 3584                          // u,v,hrw,htw(1024) + idx(512) + part(2048)
#define SCAP_F32 (SINK_SMEM_WORDS - AUX_WORDS)  // 54016 floats for S

// ---------------- scratch (static device globals; no allocation) ----------------
__device__ float    g_oklab[2][4 * 3 * NPIX];
__device__ unsigned g_mm[12];
__device__ float    g_K[NB * NB];
__device__ float    g_KC[NB * NB];
__device__ int      g_scnt[2][PCOUNT];
__device__ int      g_sidx[2][PCOUNT][256];
__device__ float    g_sw[2][PCOUNT][256];
__device__ float    g_emd[PCOUNT];

// ---------------- helpers ----------------
__device__ __forceinline__ unsigned fenc(float f) {
    unsigned u = __float_as_uint(f);
    return (u & 0x80000000u) ? ~u : (u | 0x80000000u);
}
__device__ __forceinline__ float fdec(unsigned u) {
    return __uint_as_float((u & 0x80000000u) ? (u ^ 0x80000000u) : ~u);
}
__device__ __forceinline__ float srgb_lin(float x) {
    x = fminf(fmaxf(x, 0.0f), 1.0f);
    return (x <= 0.04045f) ? x * (1.0f / 12.92f)
                           : powf((x + 0.055f) * (1.0f / 1.055f), 2.4f);
}
__device__ __forceinline__ void get_lohi(int img, float* lo, float* hi) {
#pragma unroll
    for (int c = 0; c < 3; c++) {
        float l = fdec(g_mm[img * 3 + c]) - 0.01f;
        float h = fdec(g_mm[6 + img * 3 + c]) + 0.01f;
        if (h - l < 1e-4f) { l -= 0.05f; h += 0.05f; }
        lo[c] = l; hi[c] = h;
    }
}

// ---------------- init: minmax sentinels ----------------
__global__ void init_kernel() {
    int idx = threadIdx.x;
    if (idx < 6) g_mm[idx] = 0xFFFFFFFFu;
    else if (idx < 12) g_mm[idx] = 0u;
}

// ---------------- sRGB -> OKLab + per-channel global min/max ----------------
__global__ void oklab_kernel(const float* __restrict__ ref, const float* __restrict__ tgt) {
    const int img = blockIdx.y;
    const float* __restrict__ in = img ? tgt : ref;
    float* __restrict__ outp = g_oklab[img];
    float mn0 = 1e30f, mn1 = 1e30f, mn2 = 1e30f;
    float mx0 = -1e30f, mx1 = -1e30f, mx2 = -1e30f;

    for (int idx = blockIdx.x * blockDim.x + threadIdx.x; idx < 4 * NPIX;
         idx += gridDim.x * blockDim.x) {
        int b = idx >> 16;
        int hw = idx & 65535;
        int base = b * 3 * NPIX + hw;
        float r  = srgb_lin(in[base]);
        float g  = srgb_lin(in[base + NPIX]);
        float bl = srgb_lin(in[base + 2 * NPIX]);
        float l = 0.4122214708f * r + 0.5363325363f * g + 0.0514459929f * bl;
        float m = 0.2119034982f * r + 0.6806995451f * g + 0.1073969566f * bl;
        float s = 0.0883024619f * r + 0.2817188376f * g + 0.6299787005f * bl;
        l = fmaxf(l, 0.0f); m = fmaxf(m, 0.0f); s = fmaxf(s, 0.0f);
        float lg = (l > 0.0f) ? cbrtf(fmaxf(l, 1e-12f)) : 0.0f;
        float mg = (m > 0.0f) ? cbrtf(fmaxf(m, 1e-12f)) : 0.0f;
        float sg = (s > 0.0f) ? cbrtf(fmaxf(s, 1e-12f)) : 0.0f;
        float L = 0.2104542553f * lg + 0.793617785f  * mg - 0.0040720468f * sg;
        float A = 1.9779984951f * lg - 2.428592205f  * mg + 0.4505937099f * sg;
        float B = 0.0259040371f * lg + 0.7827717662f * mg - 0.808675766f  * sg;
        outp[base] = L; outp[base + NPIX] = A; outp[base + 2 * NPIX] = B;
        mn0 = fminf(mn0, L); mx0 = fmaxf(mx0, L);
        mn1 = fminf(mn1, A); mx1 = fmaxf(mx1, A);
        mn2 = fminf(mn2, B); mx2 = fmaxf(mx2, B);
    }
#pragma unroll
    for (int o = 16; o > 0; o >>= 1) {
        mn0 = fminf(mn0, __shfl_down_sync(0xffffffffu, mn0, o));
        mn1 = fminf(mn1, __shfl_down_sync(0xffffffffu, mn1, o));
        mn2 = fminf(mn2, __shfl_down_sync(0xffffffffu, mn2, o));
        mx0 = fmaxf(mx0, __shfl_down_sync(0xffffffffu, mx0, o));
        mx1 = fmaxf(mx1, __shfl_down_sync(0xffffffffu, mx1, o));
        mx2 = fmaxf(mx2, __shfl_down_sync(0xffffffffu, mx2, o));
    }
    if ((threadIdx.x & 31) == 0) {
        atomicMin(&g_mm[img * 3 + 0], fenc(mn0));
        atomicMin(&g_mm[img * 3 + 1], fenc(mn1));
        atomicMin(&g_mm[img * 3 + 2], fenc(mn2));
        atomicMax(&g_mm[6 + img * 3 + 0], fenc(mx0));
        atomicMax(&g_mm[6 + img * 3 + 1], fenc(mx1));
        atomicMax(&g_mm[6 + img * 3 + 2], fenc(mx2));
    }
}

// ---------------- build K = exp(-cost/REG) and KC = K*cost on averaged grid ----------------
__global__ void buildK_kernel() {
    int i = blockIdx.x, j = threadIdx.x;
    float lor[3], hir[3], lot[3], hit[3];
    get_lohi(0, lor, hir);
    get_lohi(1, lot, hit);
    float step[3];
#pragma unroll
    for (int c = 0; c < 3; c++)
        step[c] = ((hir[c] - lor[c]) + (hit[c] - lot[c])) * 0.5f * 0.125f;
    int i0 = i >> 6, i1 = (i >> 3) & 7, i2 = i & 7;
    int j0 = j >> 6, j1 = (j >> 3) & 7, j2 = j & 7;
    float d0 = step[0] * (float)(i0 - j0);
    float d1 = step[1] * (float)(i1 - j1);
    float d2 = step[2] * (float)(i2 - j2);
    float dd = d0 * d0 + d1 * d1 + d2 * d2;
    float cost = (dd > 0.0f) ? sqrtf(dd) : 0.0f;
    float Kv = expf(-cost * 10.0f);        // REG = 0.1
    g_K[i * NB + j]  = Kv;
    g_KC[i * NB + j] = Kv * cost;
}

// ---------------- per-patch histograms + deterministic support-list extraction --------
__global__ void hist_kernel() {
    const int img = blockIdx.y, p = blockIdx.x, t = threadIdx.x;   // 256 threads
    __shared__ float h[NB];
    __shared__ int sca[NB], scb[NB];
    __shared__ float lo_s[3], inv_s[3];
    if (t == 0) {
        float lo[3], hi[3];
        get_lohi(img, lo, hi);
#pragma unroll
        for (int c = 0; c < 3; c++) { lo_s[c] = lo[c]; inv_s[c] = 8.0f / (hi[c] - lo[c]); }
    }
    h[t] = 0.0f; h[t + 256] = 0.0f;
    __syncthreads();

    int b = p >> 8, ph = (p >> 4) & 15, pw = p & 15;
    int py = t >> 4, px = t & 15;
    int hh = (ph << 4) + py, ww = (pw << 4) + px;
    int base = b * 3 * NPIX + hh * 256 + ww;
    const float* ok = g_oklab[img];
    float xL = ok[base], xA = ok[base + NPIX], xB = ok[base + 2 * NPIX];
    int i0 = (int)floorf((xL - lo_s[0]) * inv_s[0]); i0 = min(7, max(0, i0));
    int i1 = (int)floorf((xA - lo_s[1]) * inv_s[1]); i1 = min(7, max(0, i1));
    int i2 = (int)floorf((xB - lo_s[2]) * inv_s[2]); i2 = min(7, max(0, i2));
    atomicAdd(&h[(i0 << 6) | (i1 << 3) | i2], 1.0f);
    __syncthreads();

    // inclusive prefix scan of occupancy flags over 512 bins (Hillis-Steele, ping-pong)
    sca[t] = (h[t] > 0.0f) ? 1 : 0;
    sca[t + 256] = (h[t + 256] > 0.0f) ? 1 : 0;
    __syncthreads();
    int* src = sca; int* dst = scb;
    for (int off = 1; off < NB; off <<= 1) {
#pragma unroll
        for (int q = 0; q < 2; q++) {
            int i = t + q * 256;
            dst[i] = src[i] + ((i >= off) ? src[i - off] : 0);
        }
        __syncthreads();
        int* tmp = src; src = dst; dst = tmp;
    }

#pragma unroll
    for (int q = 0; q < 2; q++) {
        int i = t + q * 256;
        if (h[i] > 0.0f) {
            int pos = src[i] - 1;
            g_sidx[img][p][pos] = i;
            g_sw[img][p][pos]   = h[i] * (1.0f / 256.0f);
        }
    }
    if (t == 0) g_scnt[img][p] = src[NB - 1];
}

// ---------------- per-patch Sinkhorn: all 20 iterations CTA-local over sparse support --
// smem word layout: u[256] v[256] hrw[256] htw[256] idr[256] idt[256] part[8*256] S[...]
template <typename T>
__device__ void sink_body(float* sm, int p, int sr, int st, int pad) {
    float* u   = sm;
    float* v   = sm + 256;
    float* hrw = sm + 512;
    float* htw = sm + 768;
    int*   idr = (int*)(sm + 1024);
    int*   idt = (int*)(sm + 1280);
    float* part = sm + 1536;              // [8][256]
    T*     S   = (T*)(sm + AUX_WORDS);

    const int tid = threadIdx.x, lane = tid & 31, w = tid >> 5;   // 8 warps

    if (tid < sr) { idr[tid] = g_sidx[0][p][tid]; hrw[tid] = g_sw[0][p][tid]; u[tid] = 1.0f; }
    if (tid < st) { idt[tid] = g_sidx[1][p][tid]; htw[tid] = g_sw[1][p][tid]; }
    __syncthreads();

    // gather S[i][j] = K[idr[i], idt[j]]
    for (int i = w; i < sr; i += 8) {
        const float* Krow = g_K + (size_t)idr[i] * NB;
        for (int j = lane; j < st; j += 32) S[i * pad + j] = (T)Krow[idt[j]];
    }
    __syncthreads();

    const int iw0 = (sr * w) >> 3, iw1 = (sr * (w + 1)) >> 3;   // v-update i-chunk
    const int jw0 = (st * w) >> 3, jw1 = (st * (w + 1)) >> 3;   // u-update j-chunk

    for (int it = 0; it < 20; it++) {
        // v_j = ht_j / (sum_i u_i S[i][j] + eps)
        for (int j = lane; j < st; j += 32) {
            float acc = 0.0f;
            for (int i = iw0; i < iw1; i++) acc += u[i] * (float)S[i * pad + j];
            part[w * 256 + j] = acc;
        }
        __syncthreads();
        if (tid < st) {
            float d = part[tid] + part[256 + tid] + part[512 + tid] + part[768 + tid]
                    + part[1024 + tid] + part[1280 + tid] + part[1536 + tid] + part[1792 + tid];
            v[tid] = __fdividef(htw[tid], d + SINK_EPS);
        }
        __syncthreads();
        // u_i = hr_i / (sum_j v_j S[i][j] + eps)
        for (int i = lane; i < sr; i += 32) {
            float acc = 0.0f;
            for (int j = jw0; j < jw1; j++) acc += v[j] * (float)S[i * pad + j];
            part[w * 256 + i] = acc;
        }
        __syncthreads();
        if (tid < sr) {
            float d = part[tid] + part[256 + tid] + part[512 + tid] + part[768 + tid]
                    + part[1024 + tid] + part[1280 + tid] + part[1536 + tid] + part[1792 + tid];
            u[tid] = __fdividef(hrw[tid], d + SINK_EPS);
        }
        __syncthreads();
    }

    // re-gather S <- KC, then emd = sum_j v_j * (sum_i u_i KC_ij)
    for (int i = w; i < sr; i += 8) {
        const float* Crow = g_KC + (size_t)idr[i] * NB;
        for (int j = lane; j < st; j += 32) S[i * pad + j] = (T)Crow[idt[j]];
    }
    __syncthreads();
    for (int j = lane; j < st; j += 32) {
        float acc = 0.0f;
        for (int i = iw0; i < iw1; i++) acc += u[i] * (float)S[i * pad + j];
        part[w * 256 + j] = acc;
    }
    __syncthreads();
    float e = 0.0f;
    if (tid < st) {
        float d = part[tid] + part[256 + tid] + part[512 + tid] + part[768 + tid]
                + part[1024 + tid] + part[1280 + tid] + part[1536 + tid] + part[1792 + tid];
        e = v[tid] * d;
    }
    __syncthreads();
    part[tid] = e;
    __syncthreads();
    for (int o = 128; o > 0; o >>= 1) {
        if (tid < o) part[tid] += part[tid + o];
        __syncthreads();
    }
    if (tid == 0) {
        float r = part[0];
        g_emd[p] = isfinite(r) ? r : 0.0f;
    }
}

__global__ void __launch_bounds__(256) sink_kernel() {
    extern __shared__ float sm[];
    const int p = blockIdx.x;
    const int sr = g_scnt[0][p], st = g_scnt[1][p];
    const int pad = st | 1;                    // odd stride -> conflict-free both axes
    if ((long)sr * pad <= SCAP_F32) sink_body<float>(sm, p, sr, st, pad);
    else                            sink_body<__half>(sm, p, sr, st, pad);
}

// ---------------- half-pixel bilinear upsample 16x16 -> 256x256 ----------------
__global__ void upsample_kernel(float* __restrict__ out) {
    int idx = blockIdx.x * blockDim.x + threadIdx.x;
    if (idx >= 4 * NPIX) return;
    int b = idx >> 16, y = (idx >> 8) & 255, x = idx & 255;
    float fy = (y + 0.5f) * 0.0625f - 0.5f;
    float fx = (x + 0.5f) * 0.0625f - 0.5f;
    int y0 = (int)floorf(fy); float wy = fy - (float)y0;
    int x0 = (int)floorf(fx); float wx = fx - (float)x0;
    int y0c = min(15, max(0, y0)), y1c = min(15, max(0, y0 + 1));
    int x0c = min(15, max(0, x0)), x1c = min(15, max(0, x0 + 1));
    const float* e = g_emd + b * 256;
    float v00 = e[y0c * 16 + x0c], v01 = e[y0c * 16 + x1c];
    float v10 = e[y1c * 16 + x0c], v11 = e[y1c * 16 + x1c];
    v00 = isfinite(v00) ? v00 : 0.0f;
    v01 = isfinite(v01) ? v01 : 0.0f;
    v10 = isfinite(v10) ? v10 : 0.0f;
    v11 = isfinite(v11) ? v11 : 0.0f;
    float t0 = v00 + (v01 - v00) * wx;
    float t1 = v10 + (v11 - v10) * wx;
    out[idx] = t0 + (t1 - t0) * wy;
}

// ---------------- launcher ----------------
extern "C" void kernel_launch(void* const* d_in, const int* in_sizes, int n_in,
                              void* d_out, int out_size) {
    (void)in_sizes; (void)n_in; (void)out_size;
    const float* ref = (const float*)d_in[0];
    const float* tgt = (const float*)d_in[1];
    float* out = (float*)d_out;

    static int smem_set = 0;
    if (!smem_set) {
        cudaFuncSetAttribute(sink_kernel, cudaFuncAttributeMaxDynamicSharedMemorySize,
                             SINK_SMEM_BYTES);
        smem_set = 1;
    }

    init_kernel<<<1, 32>>>();
    oklab_kernel<<<dim3(256, 2), 256>>>(ref, tgt);
    buildK_kernel<<<NB, NB>>>();
    hist_kernel<<<dim3(PCOUNT, 2), 256>>>();
    sink_kernel<<<PCOUNT, 256, SINK_SMEM_BYTES>>>();
    upsample_kernel<<<(4 * NPIX + 255) / 256, 256>>>(out);
}